// round 1
// baseline (speedup 1.0000x reference)
#include <cuda_runtime.h>

#define BATCH 64
#define NQ 197
#define DIM 768
#define NH 12
#define HD 64
#define NUM_REL 732
#define MROWS (BATCH * NQ)   // 12608

static __device__ float g_Q[BATCH * NH * NQ * HD];
static __device__ float g_K[BATCH * NH * NQ * HD];
static __device__ float g_V[BATCH * NH * NQ * HD];
static __device__ float g_AO[BATCH * NQ * DIM];

// ---------------------------------------------------------------------------
// Generic fp32 GEMM: C[m][n] = sum_k A[m][k] * B[n][k]   (both K-major, K=768)
// 128x128 block tile, BK=8, 256 threads, 8x8 per-thread micro-tile.
// Epilogue functor handles bias / scaling / scatter.
// ---------------------------------------------------------------------------
template <typename Epi>
__global__ __launch_bounds__(256, 2)
void sgemm128(const float* __restrict__ A, const float* __restrict__ Bw,
              int M, Epi epi) {
    __shared__ float As[8][128];
    __shared__ float Bs[8][128];

    const int tid = threadIdx.x;
    const int tx = tid & 15;          // 0..15 -> n
    const int ty = tid >> 4;          // 0..15 -> m
    const int m0 = blockIdx.y * 128;
    const int n0 = blockIdx.x * 128;

    const int lr = tid >> 1;          // 0..127 row within tile
    const int lc = (tid & 1) * 4;     // 0 or 4

    float acc[8][8];
#pragma unroll
    for (int i = 0; i < 8; i++)
#pragma unroll
        for (int j = 0; j < 8; j++) acc[i][j] = 0.f;

    for (int k0 = 0; k0 < DIM; k0 += 8) {
        float4 av = make_float4(0.f, 0.f, 0.f, 0.f);
        int am = m0 + lr;
        if (am < M) av = *reinterpret_cast<const float4*>(A + (size_t)am * DIM + k0 + lc);
        As[lc + 0][lr] = av.x;
        As[lc + 1][lr] = av.y;
        As[lc + 2][lr] = av.z;
        As[lc + 3][lr] = av.w;

        float4 bv = *reinterpret_cast<const float4*>(Bw + (size_t)(n0 + lr) * DIM + k0 + lc);
        Bs[lc + 0][lr] = bv.x;
        Bs[lc + 1][lr] = bv.y;
        Bs[lc + 2][lr] = bv.z;
        Bs[lc + 3][lr] = bv.w;

        __syncthreads();
#pragma unroll
        for (int kk = 0; kk < 8; kk++) {
            float a[8], b[8];
#pragma unroll
            for (int i = 0; i < 8; i++) a[i] = As[kk][ty * 8 + i];
#pragma unroll
            for (int j = 0; j < 8; j++) b[j] = Bs[kk][tx * 8 + j];
#pragma unroll
            for (int i = 0; i < 8; i++)
#pragma unroll
                for (int j = 0; j < 8; j++) acc[i][j] += a[i] * b[j];
        }
        __syncthreads();
    }

#pragma unroll
    for (int i = 0; i < 8; i++) {
        int m = m0 + ty * 8 + i;
        if (m >= M) continue;
#pragma unroll
        for (int j = 0; j < 8; j++) {
            int n = n0 + tx * 8 + j;
            epi(m, n, acc[i][j]);
        }
    }
}

struct QKVEpi {
    const float* qb;
    const float* vb;
    float* Q;
    float* K;
    float* V;
    __device__ __forceinline__ void operator()(int m, int n, float acc) const {
        int part = n / DIM;
        int c = n - part * DIM;
        int h = c >> 6;
        int d = c & 63;
        int b = m / NQ;
        int r = m - b * NQ;
        int idx = ((b * NH + h) * NQ + r) * HD + d;
        if (part == 0)      Q[idx] = (acc + qb[c]) * 0.125f;   // HEAD_DIM^-0.5
        else if (part == 1) K[idx] = acc;
        else                V[idx] = acc + vb[c];
    }
};

struct ProjEpi {
    const float* pb;
    float* out;
    __device__ __forceinline__ void operator()(int m, int n, float acc) const {
        out[(size_t)m * DIM + n] = acc + pb[n];
    }
};

// ---------------------------------------------------------------------------
// Attention: one CTA per (b, h). K/V tiles in shared (stride 65 -> conflict
// free), rel-pos bias table column in shared, warp-per-query softmax.
// ---------------------------------------------------------------------------
#define KS_ROWS 224            // 7*32 rows so lane-strided reads stay in-bounds
#define ROW_STRIDE 65

__global__ __launch_bounds__(256)
void attn_kernel(const float* __restrict__ Q, const float* __restrict__ K,
                 const float* __restrict__ V, const float* __restrict__ tabg,
                 const int* __restrict__ ridx, float* __restrict__ AO) {
    extern __shared__ float sm[];
    float* Ks  = sm;                                  // 224*65
    float* Vs  = Ks + KS_ROWS * ROW_STRIDE;           // 197*65
    float* tab = Vs + NQ * ROW_STRIDE;                // 732
    float* qs  = tab + NUM_REL;                       // 8*64
    float* ps  = qs + 8 * 64;                         // 8*200

    const int bh = blockIdx.x;
    const int h = bh % NH;
    const int b = bh / NH;
    const int tid = threadIdx.x;
    const int warp = tid >> 5;
    const int lane = tid & 31;
    const size_t base = (size_t)bh * NQ * HD;

    for (int i = tid; i < NQ * HD; i += 256) {
        int r = i >> 6;
        int d = i & 63;
        Ks[r * ROW_STRIDE + d] = K[base + i];
        Vs[r * ROW_STRIDE + d] = V[base + i];
    }
    for (int i = tid; i < NUM_REL; i += 256) tab[i] = tabg[i * NH + h];
    __syncthreads();

    float* qw = qs + warp * 64;
    float* pw = ps + warp * 200;
    const float NEG_INF = __int_as_float(0xff800000u);

    for (int q = warp; q < NQ; q += 8) {
        qw[lane]      = Q[base + q * HD + lane];
        qw[lane + 32] = Q[base + q * HD + lane + 32];
        __syncwarp();

        float s[7];
#pragma unroll
        for (int kk = 0; kk < 7; kk++) s[kk] = 0.f;

#pragma unroll 16
        for (int d = 0; d < HD; d++) {
            float qd = qw[d];
#pragma unroll
            for (int kk = 0; kk < 7; kk++)
                s[kk] += qd * Ks[(kk * 32 + lane) * ROW_STRIDE + d];
        }

        const int* rrow = ridx + q * NQ;
#pragma unroll
        for (int kk = 0; kk < 7; kk++) {
            int k = kk * 32 + lane;
            if (k < NQ) s[kk] += tab[rrow[k]];
            else        s[kk] = NEG_INF;
        }

        float mx = s[0];
#pragma unroll
        for (int kk = 1; kk < 7; kk++) mx = fmaxf(mx, s[kk]);
#pragma unroll
        for (int o = 16; o > 0; o >>= 1) mx = fmaxf(mx, __shfl_xor_sync(0xffffffffu, mx, o));

        float sum = 0.f;
#pragma unroll
        for (int kk = 0; kk < 7; kk++) {
            s[kk] = __expf(s[kk] - mx);   // exp(-inf)=0 masks invalid keys
            sum += s[kk];
        }
#pragma unroll
        for (int o = 16; o > 0; o >>= 1) sum += __shfl_xor_sync(0xffffffffu, sum, o);
        float inv = __frcp_rn(sum);

#pragma unroll
        for (int kk = 0; kk < 7; kk++) {
            int k = kk * 32 + lane;
            if (k < NQ) pw[k] = s[kk] * inv;
        }
        __syncwarp();

        float a0 = 0.f, a1 = 0.f;
#pragma unroll 4
        for (int k = 0; k < NQ; k++) {
            float w = pw[k];
            a0 += w * Vs[k * ROW_STRIDE + lane];
            a1 += w * Vs[k * ROW_STRIDE + 32 + lane];
        }

        // layout [b][n][h][d] == row-major (b*NQ+q, DIM) for the proj GEMM
        size_t obase = ((size_t)(b * NQ + q) * NH + h) * HD;
        AO[obase + lane]      = a0;
        AO[obase + 32 + lane] = a1;
        __syncwarp();
    }
}

// ---------------------------------------------------------------------------
extern "C" void kernel_launch(void* const* d_in, const int* in_sizes, int n_in,
                              void* d_out, int out_size) {
    const float* x      = (const float*)d_in[0];
    const float* qkv_w  = (const float*)d_in[1];
    const float* q_bias = (const float*)d_in[2];
    const float* v_bias = (const float*)d_in[3];
    const float* rpb    = (const float*)d_in[4];
    const float* proj_w = (const float*)d_in[5];
    const float* proj_b = (const float*)d_in[6];
    const int*   ridx   = (const int*)d_in[7];
    float* out = (float*)d_out;

    float *Qp, *Kp, *Vp, *AOp;
    cudaGetSymbolAddress((void**)&Qp, g_Q);
    cudaGetSymbolAddress((void**)&Kp, g_K);
    cudaGetSymbolAddress((void**)&Vp, g_V);
    cudaGetSymbolAddress((void**)&AOp, g_AO);

    // 1) fused QKV projection -> head-split Q (scaled), K, V
    QKVEpi e1{q_bias, v_bias, Qp, Kp, Vp};
    dim3 g1(3 * DIM / 128, (MROWS + 127) / 128);
    sgemm128<QKVEpi><<<g1, 256>>>(x, qkv_w, MROWS, e1);

    // 2) attention with relative position bias
    int smem = (KS_ROWS * ROW_STRIDE + NQ * ROW_STRIDE + NUM_REL + 8 * 64 + 8 * 200) * 4;
    cudaFuncSetAttribute(attn_kernel, cudaFuncAttributeMaxDynamicSharedMemorySize, smem);
    attn_kernel<<<BATCH * NH, 256, smem>>>(Qp, Kp, Vp, rpb, ridx, AOp);

    // 3) output projection
    ProjEpi e2{proj_b, out};
    dim3 g2(DIM / 128, (MROWS + 127) / 128);
    sgemm128<ProjEpi><<<g2, 256>>>(AOp, proj_w, MROWS, e2);
}

// round 3
// speedup vs baseline: 1.7709x; 1.7709x over previous
#include <cuda_runtime.h>
#include <cuda_bf16.h>
#include <cstdint>

#define BATCH 64
#define NQ 197
#define DIM 768
#define NH 12
#define HD 64
#define NUM_REL 732
#define MROWS (BATCH * NQ)   // 12608

static __device__ float g_Q[BATCH * NH * NQ * HD];
static __device__ float g_K[BATCH * NH * NQ * HD];
static __device__ float g_V[BATCH * NH * NQ * HD];
static __device__ float g_AO[BATCH * NQ * DIM];

// ---------------------------------------------------------------------------
// helpers
// ---------------------------------------------------------------------------
__device__ __forceinline__ uint32_t smem_u32(const void* p) {
    uint32_t a;
    asm("{ .reg .u64 t; cvta.to.shared.u64 t, %1; cvt.u32.u64 %0, t; }" : "=r"(a) : "l"(p));
    return a;
}

__device__ __forceinline__ void ldsm4(uint32_t* r, uint32_t addr) {
    asm volatile("ldmatrix.sync.aligned.m8n8.x4.shared.b16 {%0,%1,%2,%3}, [%4];"
                 : "=r"(r[0]), "=r"(r[1]), "=r"(r[2]), "=r"(r[3]) : "r"(addr));
}

__device__ __forceinline__ void mma16816(float* c, const uint32_t* a, const uint32_t* b) {
    asm volatile(
        "mma.sync.aligned.m16n8k16.row.col.f32.bf16.bf16.f32 "
        "{%0,%1,%2,%3}, {%4,%5,%6,%7}, {%8,%9}, {%0,%1,%2,%3};"
        : "+f"(c[0]), "+f"(c[1]), "+f"(c[2]), "+f"(c[3])
        : "r"(a[0]), "r"(a[1]), "r"(a[2]), "r"(a[3]), "r"(b[0]), "r"(b[1]));
}

// split x,y into bf16 hi + lo packed pairs
__device__ __forceinline__ void split2(float x, float y, uint32_t& hi, uint32_t& lo) {
    __nv_bfloat162 h = __floats2bfloat162_rn(x, y);
    float hx = __bfloat162float(h.x);
    float hy = __bfloat162float(h.y);
    __nv_bfloat162 l = __floats2bfloat162_rn(x - hx, y - hy);
    hi = *reinterpret_cast<uint32_t*>(&h);
    lo = *reinterpret_cast<uint32_t*>(&l);
}

// ---------------------------------------------------------------------------
// bf16x3 tensor-core GEMM: C[m][n] = sum_k A[m][k] * B[n][k]  (K = 768)
// CTA tile 128x128, BK = 32, 8 warps (warp tile 64x32), double-buffered smem.
// smem row stride = 40 bf16 (80 B) -> ldmatrix conflict-free.
// ---------------------------------------------------------------------------
#define BK 32
#define SSTRIDE 40                        // bf16 elems per smem row
#define MAT_B (128 * SSTRIDE * 2)         // 10240 B per matrix per split
#define STAGE_B (4 * MAT_B)               // Ah, Al, Bh, Bl = 40960 B
#define GSMEM_TOTAL (2 * STAGE_B)         // 81920 B

template <typename Epi>
__global__ __launch_bounds__(256, 1)
void mgemm(const float* __restrict__ A, const float* __restrict__ Bw, int M, Epi epi) {
    extern __shared__ char smem[];
    const uint32_t sb = smem_u32(smem);
    const int tid = threadIdx.x;
    const int warp = tid >> 5;
    const int lane = tid & 31;
    const int wm = warp >> 2;          // 0..1  -> m offset 64*wm
    const int wn = warp & 3;           // 0..3  -> n offset 32*wn
    const int m0 = blockIdx.y * 128;
    const int n0 = blockIdx.x * 128;

    float acc[4][4][4];
#pragma unroll
    for (int i = 0; i < 4; i++)
#pragma unroll
        for (int j = 0; j < 4; j++)
#pragma unroll
            for (int k = 0; k < 4; k++) acc[i][j][k] = 0.f;

    // ldmatrix base offsets (bytes, ks=0, hi arrays, stage 0)
    uint32_t aoff[4], boff[2];
#pragma unroll
    for (int mf = 0; mf < 4; mf++)
        aoff[mf] = sb + (uint32_t)((wm * 64 + mf * 16 + (lane & 15)) * 80 + (lane >> 4) * 16);
#pragma unroll
    for (int pr = 0; pr < 2; pr++)
        boff[pr] = sb + 2 * MAT_B +
                   (uint32_t)((wn * 32 + pr * 16 + ((lane >> 4) * 8) + (lane & 7)) * 80 +
                              ((lane >> 3) & 1) * 16);

    const int row = (tid * 4) >> 5;    // unused placeholder removed below
    (void)row;

    float4 ar[4], br[4];

    auto gload = [&](int kt) {
#pragma unroll
        for (int i = 0; i < 4; i++) {
            int slot = tid + 256 * i;       // 0..1023
            int r = slot >> 3;              // 0..127
            int c4 = slot & 7;              // float4 within BK
            int m = m0 + r;
            if (m < M) ar[i] = *reinterpret_cast<const float4*>(A + (size_t)m * DIM + kt * BK + c4 * 4);
            else       ar[i] = make_float4(0.f, 0.f, 0.f, 0.f);
            br[i] = *reinterpret_cast<const float4*>(Bw + (size_t)(n0 + r) * DIM + kt * BK + c4 * 4);
        }
    };

    auto sstore = [&](int st) {
        char* base = smem + st * STAGE_B;
#pragma unroll
        for (int i = 0; i < 4; i++) {
            int slot = tid + 256 * i;
            int r = slot >> 3;
            int c4 = slot & 7;
            uint32_t off = (uint32_t)(r * 80 + c4 * 8);
            uint32_t h0, l0, h1, l1;
            split2(ar[i].x, ar[i].y, h0, l0);
            split2(ar[i].z, ar[i].w, h1, l1);
            *reinterpret_cast<uint2*>(base + off)         = make_uint2(h0, h1);
            *reinterpret_cast<uint2*>(base + MAT_B + off) = make_uint2(l0, l1);
            split2(br[i].x, br[i].y, h0, l0);
            split2(br[i].z, br[i].w, h1, l1);
            *reinterpret_cast<uint2*>(base + 2 * MAT_B + off) = make_uint2(h0, h1);
            *reinterpret_cast<uint2*>(base + 3 * MAT_B + off) = make_uint2(l0, l1);
        }
    };

    auto compute = [&](int st) {
        uint32_t sadd = (uint32_t)(st * STAGE_B);
#pragma unroll
        for (int ks = 0; ks < 2; ks++) {
            uint32_t ah[4][4], al[4][4];
#pragma unroll
            for (int mf = 0; mf < 4; mf++) {
                ldsm4(ah[mf], aoff[mf] + sadd + ks * 32);
                ldsm4(al[mf], aoff[mf] + MAT_B + sadd + ks * 32);
            }
            uint32_t bh[4][2], bl[4][2];
#pragma unroll
            for (int pr = 0; pr < 2; pr++) {
                uint32_t t[4];
                ldsm4(t, boff[pr] + sadd + ks * 32);
                bh[2 * pr][0] = t[0]; bh[2 * pr][1] = t[1];
                bh[2 * pr + 1][0] = t[2]; bh[2 * pr + 1][1] = t[3];
                ldsm4(t, boff[pr] + MAT_B + sadd + ks * 32);
                bl[2 * pr][0] = t[0]; bl[2 * pr][1] = t[1];
                bl[2 * pr + 1][0] = t[2]; bl[2 * pr + 1][1] = t[3];
            }
#pragma unroll
            for (int mf = 0; mf < 4; mf++)
#pragma unroll
                for (int nf = 0; nf < 4; nf++) {
                    mma16816(acc[mf][nf], ah[mf], bh[nf]);
                    mma16816(acc[mf][nf], ah[mf], bl[nf]);
                    mma16816(acc[mf][nf], al[mf], bh[nf]);
                }
        }
    };

    const int NKT = DIM / BK;   // 24
    gload(0);
    sstore(0);
    __syncthreads();

    for (int kt = 0; kt < NKT; kt++) {
        int cur = kt & 1;
        if (kt + 1 < NKT) gload(kt + 1);
        compute(cur);
        if (kt + 1 < NKT) {
            sstore((kt + 1) & 1);
            __syncthreads();
        }
    }

    // epilogue
    const int g = lane >> 2;
    const int tig = lane & 3;
#pragma unroll
    for (int mf = 0; mf < 4; mf++) {
#pragma unroll
        for (int nf = 0; nf < 4; nf++) {
            int m = m0 + wm * 64 + mf * 16 + g;
            int n = n0 + wn * 32 + nf * 8 + tig * 2;
            if (m < M)     epi(m, n, make_float2(acc[mf][nf][0], acc[mf][nf][1]));
            if (m + 8 < M) epi(m + 8, n, make_float2(acc[mf][nf][2], acc[mf][nf][3]));
        }
    }
}

struct QKVEpi2 {
    const float* qb;
    const float* vb;
    float* Q;
    float* K;
    float* V;
    __device__ __forceinline__ void operator()(int m, int n, float2 v) const {
        int part = n / DIM;
        int c = n - part * DIM;
        int h = c >> 6;
        int d = c & 63;
        int b = m / NQ;
        int r = m - b * NQ;
        size_t idx = ((size_t)((b * NH + h) * NQ + r)) * HD + d;
        if (part == 0) {
            v.x = (v.x + qb[c]) * 0.125f;
            v.y = (v.y + qb[c + 1]) * 0.125f;
            *reinterpret_cast<float2*>(Q + idx) = v;
        } else if (part == 1) {
            *reinterpret_cast<float2*>(K + idx) = v;
        } else {
            v.x += vb[c];
            v.y += vb[c + 1];
            *reinterpret_cast<float2*>(V + idx) = v;
        }
    }
};

struct ProjEpi2 {
    const float* pb;
    float* out;
    __device__ __forceinline__ void operator()(int m, int n, float2 v) const {
        v.x += pb[n];
        v.y += pb[n + 1];
        *reinterpret_cast<float2*>(out + (size_t)m * DIM + n) = v;
    }
};

// ---------------------------------------------------------------------------
// Attention: one CTA per (b, h). Unchanged from passing round-1 kernel.
// ---------------------------------------------------------------------------
#define KS_ROWS 224
#define ROW_STRIDE 65

__global__ __launch_bounds__(256)
void attn_kernel(const float* __restrict__ Q, const float* __restrict__ K,
                 const float* __restrict__ V, const float* __restrict__ tabg,
                 const int* __restrict__ ridx, float* __restrict__ AO) {
    extern __shared__ float sm[];
    float* Ks  = sm;
    float* Vs  = Ks + KS_ROWS * ROW_STRIDE;
    float* tab = Vs + NQ * ROW_STRIDE;
    float* qs  = tab + NUM_REL;
    float* ps  = qs + 8 * 64;

    const int bh = blockIdx.x;
    const int h = bh % NH;
    const int b = bh / NH;
    const int tid = threadIdx.x;
    const int warp = tid >> 5;
    const int lane = tid & 31;
    const size_t base = (size_t)bh * NQ * HD;

    for (int i = tid; i < NQ * HD; i += 256) {
        int r = i >> 6;
        int d = i & 63;
        Ks[r * ROW_STRIDE + d] = K[base + i];
        Vs[r * ROW_STRIDE + d] = V[base + i];
    }
    for (int i = tid; i < NUM_REL; i += 256) tab[i] = tabg[i * NH + h];
    __syncthreads();

    float* qw = qs + warp * 64;
    float* pw = ps + warp * 200;
    const float NEG_INF = __int_as_float(0xff800000u);

    for (int q = warp; q < NQ; q += 8) {
        qw[lane]      = Q[base + q * HD + lane];
        qw[lane + 32] = Q[base + q * HD + lane + 32];
        __syncwarp();

        float s[7];
#pragma unroll
        for (int kk = 0; kk < 7; kk++) s[kk] = 0.f;

#pragma unroll 16
        for (int d = 0; d < HD; d++) {
            float qd = qw[d];
#pragma unroll
            for (int kk = 0; kk < 7; kk++)
                s[kk] += qd * Ks[(kk * 32 + lane) * ROW_STRIDE + d];
        }

        const int* rrow = ridx + q * NQ;
#pragma unroll
        for (int kk = 0; kk < 7; kk++) {
            int k = kk * 32 + lane;
            if (k < NQ) s[kk] += tab[rrow[k]];
            else        s[kk] = NEG_INF;
        }

        float mx = s[0];
#pragma unroll
        for (int kk = 1; kk < 7; kk++) mx = fmaxf(mx, s[kk]);
#pragma unroll
        for (int o = 16; o > 0; o >>= 1) mx = fmaxf(mx, __shfl_xor_sync(0xffffffffu, mx, o));

        float sum = 0.f;
#pragma unroll
        for (int kk = 0; kk < 7; kk++) {
            s[kk] = __expf(s[kk] - mx);
            sum += s[kk];
        }
#pragma unroll
        for (int o = 16; o > 0; o >>= 1) sum += __shfl_xor_sync(0xffffffffu, sum, o);
        float inv = __frcp_rn(sum);

#pragma unroll
        for (int kk = 0; kk < 7; kk++) {
            int k = kk * 32 + lane;
            if (k < NQ) pw[k] = s[kk] * inv;
        }
        __syncwarp();

        float a0 = 0.f, a1 = 0.f;
#pragma unroll 4
        for (int k = 0; k < NQ; k++) {
            float w = pw[k];
            a0 += w * Vs[k * ROW_STRIDE + lane];
            a1 += w * Vs[k * ROW_STRIDE + 32 + lane];
        }

        size_t obase = ((size_t)(b * NQ + q) * NH + h) * HD;
        AO[obase + lane]      = a0;
        AO[obase + 32 + lane] = a1;
        __syncwarp();
    }
}

// ---------------------------------------------------------------------------
extern "C" void kernel_launch(void* const* d_in, const int* in_sizes, int n_in,
                              void* d_out, int out_size) {
    const float* x      = (const float*)d_in[0];
    const float* qkv_w  = (const float*)d_in[1];
    const float* q_bias = (const float*)d_in[2];
    const float* v_bias = (const float*)d_in[3];
    const float* rpb    = (const float*)d_in[4];
    const float* proj_w = (const float*)d_in[5];
    const float* proj_b = (const float*)d_in[6];
    const int*   ridx   = (const int*)d_in[7];
    float* out = (float*)d_out;

    float *Qp, *Kp, *Vp, *AOp;
    cudaGetSymbolAddress((void**)&Qp, g_Q);
    cudaGetSymbolAddress((void**)&Kp, g_K);
    cudaGetSymbolAddress((void**)&Vp, g_V);
    cudaGetSymbolAddress((void**)&AOp, g_AO);

    cudaFuncSetAttribute(mgemm<QKVEpi2>, cudaFuncAttributeMaxDynamicSharedMemorySize, GSMEM_TOTAL);
    cudaFuncSetAttribute(mgemm<ProjEpi2>, cudaFuncAttributeMaxDynamicSharedMemorySize, GSMEM_TOTAL);

    // 1) fused QKV projection (bf16x3 HMMA GEMM) -> head-split Q (scaled), K, V
    QKVEpi2 e1{q_bias, v_bias, Qp, Kp, Vp};
    mgemm<QKVEpi2><<<dim3(3 * DIM / 128, (MROWS + 127) / 128), 256, GSMEM_TOTAL>>>(x, qkv_w, MROWS, e1);

    // 2) attention with relative position bias
    int smem = (KS_ROWS * ROW_STRIDE + NQ * ROW_STRIDE + NUM_REL + 8 * 64 + 8 * 200) * 4;
    cudaFuncSetAttribute(attn_kernel, cudaFuncAttributeMaxDynamicSharedMemorySize, smem);
    attn_kernel<<<BATCH * NH, 256, smem>>>(Qp, Kp, Vp, rpb, ridx, AOp);

    // 3) output projection (bf16x3 HMMA GEMM)
    ProjEpi2 e2{proj_b, out};
    mgemm<ProjEpi2><<<dim3(DIM / 128, (MROWS + 127) / 128), 256, GSMEM_TOTAL>>>(AOp, proj_w, MROWS, e2);
}

// round 4
// speedup vs baseline: 3.5443x; 2.0014x over previous
#include <cuda_runtime.h>
#include <cuda_bf16.h>
#include <cstdint>

#define BATCH 64
#define NQ 197
#define DIM 768
#define NH 12
#define HD 64
#define NUM_REL 732
#define MROWS (BATCH * NQ)   // 12608

static __device__ float g_Q[BATCH * NH * NQ * HD];
static __device__ float g_K[BATCH * NH * NQ * HD];
static __device__ float g_V[BATCH * NH * NQ * HD];
static __device__ float g_AO[BATCH * NQ * DIM];

// ---------------------------------------------------------------------------
// helpers
// ---------------------------------------------------------------------------
__device__ __forceinline__ uint32_t smem_u32(const void* p) {
    uint32_t a;
    asm("{ .reg .u64 t; cvta.to.shared.u64 t, %1; cvt.u32.u64 %0, t; }" : "=r"(a) : "l"(p));
    return a;
}

__device__ __forceinline__ void ldsm4(uint32_t* r, uint32_t addr) {
    asm volatile("ldmatrix.sync.aligned.m8n8.x4.shared.b16 {%0,%1,%2,%3}, [%4];"
                 : "=r"(r[0]), "=r"(r[1]), "=r"(r[2]), "=r"(r[3]) : "r"(addr));
}

__device__ __forceinline__ void ldsm4t(uint32_t* r, uint32_t addr) {
    asm volatile("ldmatrix.sync.aligned.m8n8.x4.trans.shared.b16 {%0,%1,%2,%3}, [%4];"
                 : "=r"(r[0]), "=r"(r[1]), "=r"(r[2]), "=r"(r[3]) : "r"(addr));
}

__device__ __forceinline__ void mma16816(float* c, const uint32_t* a, const uint32_t* b) {
    asm volatile(
        "mma.sync.aligned.m16n8k16.row.col.f32.bf16.bf16.f32 "
        "{%0,%1,%2,%3}, {%4,%5,%6,%7}, {%8,%9}, {%0,%1,%2,%3};"
        : "+f"(c[0]), "+f"(c[1]), "+f"(c[2]), "+f"(c[3])
        : "r"(a[0]), "r"(a[1]), "r"(a[2]), "r"(a[3]), "r"(b[0]), "r"(b[1]));
}

__device__ __forceinline__ void split2(float x, float y, uint32_t& hi, uint32_t& lo) {
    __nv_bfloat162 h = __floats2bfloat162_rn(x, y);
    float hx = __bfloat162float(h.x);
    float hy = __bfloat162float(h.y);
    __nv_bfloat162 l = __floats2bfloat162_rn(x - hx, y - hy);
    hi = *reinterpret_cast<uint32_t*>(&h);
    lo = *reinterpret_cast<uint32_t*>(&l);
}

// ---------------------------------------------------------------------------
// bf16x3 tensor-core GEMM (unchanged from passing round-3 kernel)
// ---------------------------------------------------------------------------
#define BK 32
#define SSTRIDE 40
#define MAT_B (128 * SSTRIDE * 2)
#define STAGE_B (4 * MAT_B)
#define GSMEM_TOTAL (2 * STAGE_B)

template <typename Epi>
__global__ __launch_bounds__(256, 1)
void mgemm(const float* __restrict__ A, const float* __restrict__ Bw, int M, Epi epi) {
    extern __shared__ char smem[];
    const uint32_t sb = smem_u32(smem);
    const int tid = threadIdx.x;
    const int warp = tid >> 5;
    const int lane = tid & 31;
    const int wm = warp >> 2;
    const int wn = warp & 3;
    const int m0 = blockIdx.y * 128;
    const int n0 = blockIdx.x * 128;

    float acc[4][4][4];
#pragma unroll
    for (int i = 0; i < 4; i++)
#pragma unroll
        for (int j = 0; j < 4; j++)
#pragma unroll
            for (int k = 0; k < 4; k++) acc[i][j][k] = 0.f;

    uint32_t aoff[4], boff[2];
#pragma unroll
    for (int mf = 0; mf < 4; mf++)
        aoff[mf] = sb + (uint32_t)((wm * 64 + mf * 16 + (lane & 15)) * 80 + (lane >> 4) * 16);
#pragma unroll
    for (int pr = 0; pr < 2; pr++)
        boff[pr] = sb + 2 * MAT_B +
                   (uint32_t)((wn * 32 + pr * 16 + ((lane >> 4) * 8) + (lane & 7)) * 80 +
                              ((lane >> 3) & 1) * 16);

    float4 ar[4], br[4];

    auto gload = [&](int kt) {
#pragma unroll
        for (int i = 0; i < 4; i++) {
            int slot = tid + 256 * i;
            int r = slot >> 3;
            int c4 = slot & 7;
            int m = m0 + r;
            if (m < M) ar[i] = *reinterpret_cast<const float4*>(A + (size_t)m * DIM + kt * BK + c4 * 4);
            else       ar[i] = make_float4(0.f, 0.f, 0.f, 0.f);
            br[i] = *reinterpret_cast<const float4*>(Bw + (size_t)(n0 + r) * DIM + kt * BK + c4 * 4);
        }
    };

    auto sstore = [&](int st) {
        char* base = smem + st * STAGE_B;
#pragma unroll
        for (int i = 0; i < 4; i++) {
            int slot = tid + 256 * i;
            int r = slot >> 3;
            int c4 = slot & 7;
            uint32_t off = (uint32_t)(r * 80 + c4 * 8);
            uint32_t h0, l0, h1, l1;
            split2(ar[i].x, ar[i].y, h0, l0);
            split2(ar[i].z, ar[i].w, h1, l1);
            *reinterpret_cast<uint2*>(base + off)         = make_uint2(h0, h1);
            *reinterpret_cast<uint2*>(base + MAT_B + off) = make_uint2(l0, l1);
            split2(br[i].x, br[i].y, h0, l0);
            split2(br[i].z, br[i].w, h1, l1);
            *reinterpret_cast<uint2*>(base + 2 * MAT_B + off) = make_uint2(h0, h1);
            *reinterpret_cast<uint2*>(base + 3 * MAT_B + off) = make_uint2(l0, l1);
        }
    };

    auto compute = [&](int st) {
        uint32_t sadd = (uint32_t)(st * STAGE_B);
#pragma unroll
        for (int ks = 0; ks < 2; ks++) {
            uint32_t ah[4][4], al[4][4];
#pragma unroll
            for (int mf = 0; mf < 4; mf++) {
                ldsm4(ah[mf], aoff[mf] + sadd + ks * 32);
                ldsm4(al[mf], aoff[mf] + MAT_B + sadd + ks * 32);
            }
            uint32_t bh[4][2], bl[4][2];
#pragma unroll
            for (int pr = 0; pr < 2; pr++) {
                uint32_t t[4];
                ldsm4(t, boff[pr] + sadd + ks * 32);
                bh[2 * pr][0] = t[0]; bh[2 * pr][1] = t[1];
                bh[2 * pr + 1][0] = t[2]; bh[2 * pr + 1][1] = t[3];
                ldsm4(t, boff[pr] + MAT_B + sadd + ks * 32);
                bl[2 * pr][0] = t[0]; bl[2 * pr][1] = t[1];
                bl[2 * pr + 1][0] = t[2]; bl[2 * pr + 1][1] = t[3];
            }
#pragma unroll
            for (int mf = 0; mf < 4; mf++)
#pragma unroll
                for (int nf = 0; nf < 4; nf++) {
                    mma16816(acc[mf][nf], ah[mf], bh[nf]);
                    mma16816(acc[mf][nf], ah[mf], bl[nf]);
                    mma16816(acc[mf][nf], al[mf], bh[nf]);
                }
        }
    };

    const int NKT = DIM / BK;
    gload(0);
    sstore(0);
    __syncthreads();

    for (int kt = 0; kt < NKT; kt++) {
        int cur = kt & 1;
        if (kt + 1 < NKT) gload(kt + 1);
        compute(cur);
        if (kt + 1 < NKT) {
            sstore((kt + 1) & 1);
            __syncthreads();
        }
    }

    const int g = lane >> 2;
    const int tig = lane & 3;
#pragma unroll
    for (int mf = 0; mf < 4; mf++) {
#pragma unroll
        for (int nf = 0; nf < 4; nf++) {
            int m = m0 + wm * 64 + mf * 16 + g;
            int n = n0 + wn * 32 + nf * 8 + tig * 2;
            if (m < M)     epi(m, n, make_float2(acc[mf][nf][0], acc[mf][nf][1]));
            if (m + 8 < M) epi(m + 8, n, make_float2(acc[mf][nf][2], acc[mf][nf][3]));
        }
    }
}

struct QKVEpi2 {
    const float* qb;
    const float* vb;
    float* Q;
    float* K;
    float* V;
    __device__ __forceinline__ void operator()(int m, int n, float2 v) const {
        int part = n / DIM;
        int c = n - part * DIM;
        int h = c >> 6;
        int d = c & 63;
        int b = m / NQ;
        int r = m - b * NQ;
        size_t idx = ((size_t)((b * NH + h) * NQ + r)) * HD + d;
        if (part == 0) {
            v.x = (v.x + qb[c]) * 0.125f;
            v.y = (v.y + qb[c + 1]) * 0.125f;
            *reinterpret_cast<float2*>(Q + idx) = v;
        } else if (part == 1) {
            *reinterpret_cast<float2*>(K + idx) = v;
        } else {
            v.x += vb[c];
            v.y += vb[c + 1];
            *reinterpret_cast<float2*>(V + idx) = v;
        }
    }
};

struct ProjEpi2 {
    const float* pb;
    float* out;
    __device__ __forceinline__ void operator()(int m, int n, float2 v) const {
        v.x += pb[n];
        v.y += pb[n + 1];
        *reinterpret_cast<float2*>(out + (size_t)m * DIM + n) = v;
    }
};

// ---------------------------------------------------------------------------
// Tensor-core attention: one CTA per (b,h). bf16x3 for S = Q*K^T and O = P*V.
// Q/K/V staged in smem as bf16 hi/lo, 208 rows padded, 144-byte row stride.
// P is converted C-frag -> A-frag entirely in registers.
// ---------------------------------------------------------------------------
#define NQP 208
#define KSTR_B 144                       // bytes per row (72 bf16)
#define AMAT_B (NQP * KSTR_B)            // 29952
#define ASMEM_TOTAL (6 * AMAT_B + NUM_REL * 4)   // 182640

__global__ __launch_bounds__(256, 1)
void attn_mma(const float* __restrict__ Q, const float* __restrict__ K,
              const float* __restrict__ V, const float* __restrict__ tabg,
              const int* __restrict__ ridx, float* __restrict__ AO) {
    extern __shared__ char sm[];
    const uint32_t sb = smem_u32(sm);
    const uint32_t Qhi = sb;
    const uint32_t Qlo = sb + AMAT_B;
    const uint32_t Khi = sb + 2 * AMAT_B;
    const uint32_t Klo = sb + 3 * AMAT_B;
    const uint32_t Vhi = sb + 4 * AMAT_B;
    const uint32_t Vlo = sb + 5 * AMAT_B;
    float* tab = reinterpret_cast<float*>(sm + 6 * AMAT_B);

    const int bh = blockIdx.x;
    const int h = bh % NH;
    const int b = bh / NH;
    const int tid = threadIdx.x;
    const int warp = tid >> 5;
    const int lane = tid & 31;
    const int g = lane >> 2;
    const int tig = lane & 3;
    const size_t base = (size_t)bh * NQ * HD;

    // ---- stage Q/K/V as bf16 hi/lo ----
    for (int i = tid; i < NQ * 16; i += 256) {
        int r = i >> 4;
        int c4 = i & 15;                       // float4 within the 64-dim row
        uint32_t off = (uint32_t)(r * KSTR_B + c4 * 8);
        uint32_t h0, l0, h1, l1;
        float4 qv = *reinterpret_cast<const float4*>(Q + base + r * HD + c4 * 4);
        split2(qv.x, qv.y, h0, l0); split2(qv.z, qv.w, h1, l1);
        *reinterpret_cast<uint2*>(sm + (Qhi - sb) + off) = make_uint2(h0, h1);
        *reinterpret_cast<uint2*>(sm + (Qlo - sb) + off) = make_uint2(l0, l1);
        float4 kv = *reinterpret_cast<const float4*>(K + base + r * HD + c4 * 4);
        split2(kv.x, kv.y, h0, l0); split2(kv.z, kv.w, h1, l1);
        *reinterpret_cast<uint2*>(sm + (Khi - sb) + off) = make_uint2(h0, h1);
        *reinterpret_cast<uint2*>(sm + (Klo - sb) + off) = make_uint2(l0, l1);
        float4 vv = *reinterpret_cast<const float4*>(V + base + r * HD + c4 * 4);
        split2(vv.x, vv.y, h0, l0); split2(vv.z, vv.w, h1, l1);
        *reinterpret_cast<uint2*>(sm + (Vhi - sb) + off) = make_uint2(h0, h1);
        *reinterpret_cast<uint2*>(sm + (Vlo - sb) + off) = make_uint2(l0, l1);
    }
    // zero pad rows 197..207 (full 144-byte rows) in all six arrays
    for (int i = tid; i < 11 * 18; i += 256) {
        int r = 197 + i / 18;
        int c = i % 18;
        uint32_t off = (uint32_t)(r * KSTR_B + c * 8);
#pragma unroll
        for (int a = 0; a < 6; a++)
            *reinterpret_cast<uint2*>(sm + a * AMAT_B + off) = make_uint2(0u, 0u);
    }
    for (int i = tid; i < NUM_REL; i += 256) tab[i] = tabg[i * NH + h];
    __syncthreads();

    for (int blk = warp; blk < 13; blk += 8) {
        // ---- S = Q @ K^T (bf16x3), S acc: 26 n-chunks x 4 ----
        float s[26][4];
#pragma unroll
        for (int nc = 0; nc < 26; nc++)
#pragma unroll
            for (int e = 0; e < 4; e++) s[nc][e] = 0.f;

        const uint32_t qrow = (uint32_t)((blk * 16 + (lane & 15)) * KSTR_B + (lane >> 4) * 16);
        const uint32_t krow = (uint32_t)(((lane >> 4) * 8 + (lane & 7)) * KSTR_B + ((lane >> 3) & 1) * 16);

#pragma unroll
        for (int kc = 0; kc < 4; kc++) {
            uint32_t qh[4], ql[4];
            ldsm4(qh, Qhi + qrow + kc * 32);
            ldsm4(ql, Qlo + qrow + kc * 32);
#pragma unroll
            for (int np = 0; np < 13; np++) {
                uint32_t th[4], tl[4];
                ldsm4(th, Khi + krow + (uint32_t)(np * 16 * KSTR_B) + kc * 32);
                ldsm4(tl, Klo + krow + (uint32_t)(np * 16 * KSTR_B) + kc * 32);
                mma16816(s[2 * np],     qh, th);
                mma16816(s[2 * np],     qh, tl);
                mma16816(s[2 * np],     ql, th);
                mma16816(s[2 * np + 1], qh, th + 2);
                mma16816(s[2 * np + 1], qh, tl + 2);
                mma16816(s[2 * np + 1], ql, th + 2);
            }
        }

        // ---- bias + mask ----
        const int q0 = blk * 16 + g;
        const int q1 = q0 + 8;
        const int* r0 = ridx + (size_t)min(q0, NQ - 1) * NQ;
        const int* r1 = ridx + (size_t)min(q1, NQ - 1) * NQ;
#pragma unroll
        for (int nc = 0; nc < 26; nc++) {
            int n0 = nc * 8 + tig * 2;
            if (n0 < NQ) { s[nc][0] += tab[r0[n0]]; s[nc][2] += tab[r1[n0]]; }
            else         { s[nc][0] = -1e30f;       s[nc][2] = -1e30f; }
            int n1 = n0 + 1;
            if (n1 < NQ) { s[nc][1] += tab[r0[n1]]; s[nc][3] += tab[r1[n1]]; }
            else         { s[nc][1] = -1e30f;       s[nc][3] = -1e30f; }
        }

        // ---- softmax (rows live in lane quads) ----
        float mx0 = -1e30f, mx1 = -1e30f;
#pragma unroll
        for (int nc = 0; nc < 26; nc++) {
            mx0 = fmaxf(mx0, fmaxf(s[nc][0], s[nc][1]));
            mx1 = fmaxf(mx1, fmaxf(s[nc][2], s[nc][3]));
        }
        mx0 = fmaxf(mx0, __shfl_xor_sync(0xffffffffu, mx0, 1));
        mx0 = fmaxf(mx0, __shfl_xor_sync(0xffffffffu, mx0, 2));
        mx1 = fmaxf(mx1, __shfl_xor_sync(0xffffffffu, mx1, 1));
        mx1 = fmaxf(mx1, __shfl_xor_sync(0xffffffffu, mx1, 2));

        float sum0 = 0.f, sum1 = 0.f;
#pragma unroll
        for (int nc = 0; nc < 26; nc++) {
            s[nc][0] = __expf(s[nc][0] - mx0);
            s[nc][1] = __expf(s[nc][1] - mx0);
            s[nc][2] = __expf(s[nc][2] - mx1);
            s[nc][3] = __expf(s[nc][3] - mx1);
            sum0 += s[nc][0] + s[nc][1];
            sum1 += s[nc][2] + s[nc][3];
        }
        sum0 += __shfl_xor_sync(0xffffffffu, sum0, 1);
        sum0 += __shfl_xor_sync(0xffffffffu, sum0, 2);
        sum1 += __shfl_xor_sync(0xffffffffu, sum1, 1);
        sum1 += __shfl_xor_sync(0xffffffffu, sum1, 2);
        float inv0 = __frcp_rn(sum0);
        float inv1 = __frcp_rn(sum1);
#pragma unroll
        for (int nc = 0; nc < 26; nc++) {
            s[nc][0] *= inv0; s[nc][1] *= inv0;
            s[nc][2] *= inv1; s[nc][3] *= inv1;
        }

        // ---- O = P @ V (bf16x3), P frags from registers, V via ldmatrix.trans ----
        float o[8][4];
#pragma unroll
        for (int nd = 0; nd < 8; nd++)
#pragma unroll
            for (int e = 0; e < 4; e++) o[nd][e] = 0.f;

        const uint32_t vrow = (uint32_t)((((lane >> 3) & 1) * 8 + (lane & 7)) * KSTR_B + (lane >> 4) * 16);

#pragma unroll
        for (int kc = 0; kc < 13; kc++) {
            uint32_t ph[4], pl[4];
            split2(s[2 * kc][0],     s[2 * kc][1],     ph[0], pl[0]);
            split2(s[2 * kc][2],     s[2 * kc][3],     ph[1], pl[1]);
            split2(s[2 * kc + 1][0], s[2 * kc + 1][1], ph[2], pl[2]);
            split2(s[2 * kc + 1][2], s[2 * kc + 1][3], ph[3], pl[3]);
#pragma unroll
            for (int dg = 0; dg < 4; dg++) {
                uint32_t bh4[4], bl4[4];
                ldsm4t(bh4, Vhi + vrow + (uint32_t)(kc * 16 * KSTR_B) + dg * 32);
                ldsm4t(bl4, Vlo + vrow + (uint32_t)(kc * 16 * KSTR_B) + dg * 32);
                mma16816(o[2 * dg],     ph, bh4);
                mma16816(o[2 * dg],     ph, bl4);
                mma16816(o[2 * dg],     pl, bh4);
                mma16816(o[2 * dg + 1], ph, bh4 + 2);
                mma16816(o[2 * dg + 1], ph, bl4 + 2);
                mma16816(o[2 * dg + 1], pl, bh4 + 2);
            }
        }

        // ---- store: AO layout [b][q][h][d] ----
        if (q0 < NQ) {
            size_t ob = ((size_t)(b * NQ + q0) * NH + h) * HD + tig * 2;
#pragma unroll
            for (int nd = 0; nd < 8; nd++)
                *reinterpret_cast<float2*>(AO + ob + nd * 8) = make_float2(o[nd][0], o[nd][1]);
        }
        if (q1 < NQ) {
            size_t ob = ((size_t)(b * NQ + q1) * NH + h) * HD + tig * 2;
#pragma unroll
            for (int nd = 0; nd < 8; nd++)
                *reinterpret_cast<float2*>(AO + ob + nd * 8) = make_float2(o[nd][2], o[nd][3]);
        }
    }
}

// ---------------------------------------------------------------------------
extern "C" void kernel_launch(void* const* d_in, const int* in_sizes, int n_in,
                              void* d_out, int out_size) {
    const float* x      = (const float*)d_in[0];
    const float* qkv_w  = (const float*)d_in[1];
    const float* q_bias = (const float*)d_in[2];
    const float* v_bias = (const float*)d_in[3];
    const float* rpb    = (const float*)d_in[4];
    const float* proj_w = (const float*)d_in[5];
    const float* proj_b = (const float*)d_in[6];
    const int*   ridx   = (const int*)d_in[7];
    float* out = (float*)d_out;

    float *Qp, *Kp, *Vp, *AOp;
    cudaGetSymbolAddress((void**)&Qp, g_Q);
    cudaGetSymbolAddress((void**)&Kp, g_K);
    cudaGetSymbolAddress((void**)&Vp, g_V);
    cudaGetSymbolAddress((void**)&AOp, g_AO);

    cudaFuncSetAttribute(mgemm<QKVEpi2>, cudaFuncAttributeMaxDynamicSharedMemorySize, GSMEM_TOTAL);
    cudaFuncSetAttribute(mgemm<ProjEpi2>, cudaFuncAttributeMaxDynamicSharedMemorySize, GSMEM_TOTAL);
    cudaFuncSetAttribute(attn_mma, cudaFuncAttributeMaxDynamicSharedMemorySize, ASMEM_TOTAL);

    // 1) fused QKV projection (bf16x3 HMMA GEMM) -> head-split Q (scaled), K, V
    QKVEpi2 e1{q_bias, v_bias, Qp, Kp, Vp};
    mgemm<QKVEpi2><<<dim3(3 * DIM / 128, (MROWS + 127) / 128), 256, GSMEM_TOTAL>>>(x, qkv_w, MROWS, e1);

    // 2) tensor-core attention with relative position bias
    attn_mma<<<BATCH * NH, 256, ASMEM_TOTAL>>>(Qp, Kp, Vp, rpb, ridx, AOp);

    // 3) output projection (bf16x3 HMMA GEMM)
    ProjEpi2 e2{proj_b, out};
    mgemm<ProjEpi2><<<dim3(DIM / 128, (MROWS + 127) / 128), 256, GSMEM_TOTAL>>>(AOp, proj_w, MROWS, e2);
}